// round 6
// baseline (speedup 1.0000x reference)
#include <cuda_runtime.h>
#include <cstddef>

// Problem constants
#define NB  4
#define CC  256
#define HWD 4096

// Scratch (static device memory — no allocation allowed)
__device__ float g_theta[NB * CC * HWD];                    // 16 MB
__device__ float g_phi[NB * CC * HWD];                      // 16 MB
__device__ float g_expS[(size_t)NB * HWD * HWD];            // 256 MB
__device__ float g_f[NB * CC * HWD];                        // 16 MB

// ---------------------------------------------------------------------------
// Kernel 1/3/5: 1x1 conv as GEMM.  out[n,o,p] = sum_k W[o,k]*X[n,k,p] + b[o]
//               (+ optional residual R[n,o,p])
// Tile 128x128, BK=16, 256 threads, 8x8 micro in 2x2 quadrants.
// W tile is transposed on load (k-contiguous in global), X tile direct.
// ---------------------------------------------------------------------------
__global__ __launch_bounds__(256, 2)
void conv_gemm_kernel(const float* __restrict__ W,
                      const float* __restrict__ bias,
                      const float* __restrict__ X,
                      const float* __restrict__ resid,   // may be null
                      float* __restrict__ out)
{
    __shared__ float Ws[16][132];   // [k][o_row], padded
    __shared__ float Xs[16][128];   // [k][p]

    const int t  = threadIdx.x;
    const int tx = t & 15;
    const int ty = t >> 4;
    const int p0 = blockIdx.x * 128;
    const int o0 = blockIdx.y * 128;
    const int n  = blockIdx.z;

    const float* Xn = X + (size_t)n * CC * HWD;

    float acc[2][2][4][4];
#pragma unroll
    for (int a = 0; a < 2; ++a)
#pragma unroll
        for (int b = 0; b < 2; ++b)
#pragma unroll
            for (int i = 0; i < 4; ++i)
#pragma unroll
                for (int j = 0; j < 4; ++j) acc[a][b][i][j] = 0.f;

    for (int kt = 0; kt < CC; kt += 16) {
        // W tile (transpose on load): rows o0..o0+127, cols kt..kt+15
#pragma unroll
        for (int i = 0; i < 2; ++i) {
            int v  = t + i * 256;
            int r  = v >> 2;
            int kk = (v & 3) << 2;
            float4 w4 = *(const float4*)(W + (size_t)(o0 + r) * CC + kt + kk);
            Ws[kk + 0][r] = w4.x; Ws[kk + 1][r] = w4.y;
            Ws[kk + 2][r] = w4.z; Ws[kk + 3][r] = w4.w;
        }
        // X tile (direct): rows kt..kt+15, cols p0..p0+127
#pragma unroll
        for (int i = 0; i < 2; ++i) {
            int v  = t + i * 256;
            int k  = v >> 5;
            int p4 = (v & 31) << 2;
            *(float4*)&Xs[k][p4] =
                *(const float4*)(Xn + (size_t)(kt + k) * HWD + p0 + p4);
        }
        __syncthreads();
#pragma unroll
        for (int k = 0; k < 16; ++k) {
            float a[2][4], b[2][4];
            *(float4*)a[0] = *(const float4*)&Ws[k][ty * 4];
            *(float4*)a[1] = *(const float4*)&Ws[k][64 + ty * 4];
            *(float4*)b[0] = *(const float4*)&Xs[k][tx * 4];
            *(float4*)b[1] = *(const float4*)&Xs[k][64 + tx * 4];
#pragma unroll
            for (int ih = 0; ih < 2; ++ih)
#pragma unroll
                for (int jh = 0; jh < 2; ++jh)
#pragma unroll
                    for (int i = 0; i < 4; ++i)
#pragma unroll
                        for (int j = 0; j < 4; ++j)
                            acc[ih][jh][i][j] += a[ih][i] * b[jh][j];
        }
        __syncthreads();
    }

    // Epilogue: bias (+ residual), write float4 per row-quadrant
#pragma unroll
    for (int ih = 0; ih < 2; ++ih) {
#pragma unroll
        for (int i = 0; i < 4; ++i) {
            const int row = o0 + ih * 64 + ty * 4 + i;
            const float bv = bias[row];
#pragma unroll
            for (int jh = 0; jh < 2; ++jh) {
                const int col = p0 + jh * 64 + tx * 4;
                float4 v;
                v.x = acc[ih][jh][i][0] + bv;
                v.y = acc[ih][jh][i][1] + bv;
                v.z = acc[ih][jh][i][2] + bv;
                v.w = acc[ih][jh][i][3] + bv;
                const size_t off = (size_t)n * CC * HWD + (size_t)row * HWD + col;
                if (resid) {
                    float4 rr = *(const float4*)(resid + off);
                    v.x += rr.x; v.y += rr.y; v.z += rr.z; v.w += rr.w;
                }
                *(float4*)(out + off) = v;
            }
        }
    }
}

// ---------------------------------------------------------------------------
// Kernel 2: expS[n,p,q] = exp( (sum_c theta[n,c,p]*phi[n,c,q]) / 16 )
// A^T*B GEMM: both tiles direct-stored (position dim contiguous). K = C = 256.
// No max-subtraction: |score| <= ~16, exp() safe in fp32.
// ---------------------------------------------------------------------------
__global__ __launch_bounds__(256, 2)
void scores_exp_kernel(const float* __restrict__ theta,
                       const float* __restrict__ phi,
                       float* __restrict__ expS)
{
    __shared__ float As[16][128];   // [c][p]
    __shared__ float Bs[16][128];   // [c][q]

    const int t  = threadIdx.x;
    const int tx = t & 15;
    const int ty = t >> 4;
    const int q0 = blockIdx.x * 128;
    const int p0 = blockIdx.y * 128;
    const int n  = blockIdx.z;

    const float* Tn = theta + (size_t)n * CC * HWD;
    const float* Pn = phi   + (size_t)n * CC * HWD;

    float acc[2][2][4][4];
#pragma unroll
    for (int a = 0; a < 2; ++a)
#pragma unroll
        for (int b = 0; b < 2; ++b)
#pragma unroll
            for (int i = 0; i < 4; ++i)
#pragma unroll
                for (int j = 0; j < 4; ++j) acc[a][b][i][j] = 0.f;

    for (int kt = 0; kt < CC; kt += 16) {
#pragma unroll
        for (int i = 0; i < 2; ++i) {
            int v  = t + i * 256;
            int k  = v >> 5;
            int p4 = (v & 31) << 2;
            *(float4*)&As[k][p4] =
                *(const float4*)(Tn + (size_t)(kt + k) * HWD + p0 + p4);
            *(float4*)&Bs[k][p4] =
                *(const float4*)(Pn + (size_t)(kt + k) * HWD + q0 + p4);
        }
        __syncthreads();
#pragma unroll
        for (int k = 0; k < 16; ++k) {
            float a[2][4], b[2][4];
            *(float4*)a[0] = *(const float4*)&As[k][ty * 4];
            *(float4*)a[1] = *(const float4*)&As[k][64 + ty * 4];
            *(float4*)b[0] = *(const float4*)&Bs[k][tx * 4];
            *(float4*)b[1] = *(const float4*)&Bs[k][64 + tx * 4];
#pragma unroll
            for (int ih = 0; ih < 2; ++ih)
#pragma unroll
                for (int jh = 0; jh < 2; ++jh)
#pragma unroll
                    for (int i = 0; i < 4; ++i)
#pragma unroll
                        for (int j = 0; j < 4; ++j)
                            acc[ih][jh][i][j] += a[ih][i] * b[jh][j];
        }
        __syncthreads();
    }

    float* Sn = expS + (size_t)n * HWD * HWD;
#pragma unroll
    for (int ih = 0; ih < 2; ++ih) {
#pragma unroll
        for (int i = 0; i < 4; ++i) {
            const int row = p0 + ih * 64 + ty * 4 + i;
#pragma unroll
            for (int jh = 0; jh < 2; ++jh) {
                const int col = q0 + jh * 64 + tx * 4;
                float4 v;
                v.x = __expf(acc[ih][jh][i][0] * 0.0625f);
                v.y = __expf(acc[ih][jh][i][1] * 0.0625f);
                v.z = __expf(acc[ih][jh][i][2] * 0.0625f);
                v.w = __expf(acc[ih][jh][i][3] * 0.0625f);
                *(float4*)(Sn + (size_t)row * HWD + col) = v;
            }
        }
    }
}

// ---------------------------------------------------------------------------
// Kernel 4: f[n,c,p] = (sum_q x[n,c,q] * expS[n,p,q]) / (sum_q expS[n,p,q])
// A*B^T GEMM, K = HW = 4096. Both operands k-contiguous -> transpose-on-load.
// Softmax denominator accumulated for free in bsum (each thread already reads
// the full q-range of its output columns' expS rows).
// ---------------------------------------------------------------------------
__global__ __launch_bounds__(256, 2)
void pv_kernel(const float* __restrict__ x,
               const float* __restrict__ expS,
               float* __restrict__ f)
{
    __shared__ float As[16][132];   // [q][c], padded
    __shared__ float Bs[16][132];   // [q][p], padded

    const int t  = threadIdx.x;
    const int tx = t & 15;
    const int ty = t >> 4;
    const int p0 = blockIdx.x * 128;   // output columns (query positions)
    const int c0 = blockIdx.y * 128;   // output rows (channels)
    const int n  = blockIdx.z;

    const float* Xn = x    + (size_t)n * CC * HWD;
    const float* Sn = expS + (size_t)n * HWD * HWD;

    float acc[2][2][4][4];
#pragma unroll
    for (int a = 0; a < 2; ++a)
#pragma unroll
        for (int b = 0; b < 2; ++b)
#pragma unroll
            for (int i = 0; i < 4; ++i)
#pragma unroll
                for (int j = 0; j < 4; ++j) acc[a][b][i][j] = 0.f;
    float bsum[2][4];
#pragma unroll
    for (int jh = 0; jh < 2; ++jh)
#pragma unroll
        for (int j = 0; j < 4; ++j) bsum[jh][j] = 0.f;

    for (int kt = 0; kt < HWD; kt += 16) {
#pragma unroll
        for (int i = 0; i < 2; ++i) {
            int v  = t + i * 256;
            int r  = v >> 2;
            int kk = (v & 3) << 2;
            float4 a4 = *(const float4*)(Xn + (size_t)(c0 + r) * HWD + kt + kk);
            As[kk + 0][r] = a4.x; As[kk + 1][r] = a4.y;
            As[kk + 2][r] = a4.z; As[kk + 3][r] = a4.w;
            float4 b4 = *(const float4*)(Sn + (size_t)(p0 + r) * HWD + kt + kk);
            Bs[kk + 0][r] = b4.x; Bs[kk + 1][r] = b4.y;
            Bs[kk + 2][r] = b4.z; Bs[kk + 3][r] = b4.w;
        }
        __syncthreads();
#pragma unroll
        for (int k = 0; k < 16; ++k) {
            float a[2][4], b[2][4];
            *(float4*)a[0] = *(const float4*)&As[k][ty * 4];
            *(float4*)a[1] = *(const float4*)&As[k][64 + ty * 4];
            *(float4*)b[0] = *(const float4*)&Bs[k][tx * 4];
            *(float4*)b[1] = *(const float4*)&Bs[k][64 + tx * 4];
#pragma unroll
            for (int jh = 0; jh < 2; ++jh)
#pragma unroll
                for (int j = 0; j < 4; ++j) bsum[jh][j] += b[jh][j];
#pragma unroll
            for (int ih = 0; ih < 2; ++ih)
#pragma unroll
                for (int jh = 0; jh < 2; ++jh)
#pragma unroll
                    for (int i = 0; i < 4; ++i)
#pragma unroll
                        for (int j = 0; j < 4; ++j)
                            acc[ih][jh][i][j] += a[ih][i] * b[jh][j];
        }
        __syncthreads();
    }

    float inv[2][4];
#pragma unroll
    for (int jh = 0; jh < 2; ++jh)
#pragma unroll
        for (int j = 0; j < 4; ++j) inv[jh][j] = 1.0f / bsum[jh][j];

    float* Fn = f + (size_t)n * CC * HWD;
#pragma unroll
    for (int ih = 0; ih < 2; ++ih) {
#pragma unroll
        for (int i = 0; i < 4; ++i) {
            const int row = c0 + ih * 64 + ty * 4 + i;
#pragma unroll
            for (int jh = 0; jh < 2; ++jh) {
                const int col = p0 + jh * 64 + tx * 4;
                float4 v;
                v.x = acc[ih][jh][i][0] * inv[jh][0];
                v.y = acc[ih][jh][i][1] * inv[jh][1];
                v.z = acc[ih][jh][i][2] * inv[jh][2];
                v.w = acc[ih][jh][i][3] * inv[jh][3];
                *(float4*)(Fn + (size_t)row * HWD + col) = v;
            }
        }
    }
}

// ---------------------------------------------------------------------------
// Launch: theta & phi convs -> scores+exp -> PV (with fused softmax denom)
//         -> final conv with residual into d_out. Stream order = dependency.
// ---------------------------------------------------------------------------
extern "C" void kernel_launch(void* const* d_in, const int* in_sizes, int n_in,
                              void* d_out, int out_size)
{
    (void)in_sizes; (void)n_in; (void)out_size;
    const float* x       = (const float*)d_in[0];
    const float* theta_w = (const float*)d_in[1];
    const float* theta_b = (const float*)d_in[2];
    const float* phi_w   = (const float*)d_in[3];
    const float* phi_b   = (const float*)d_in[4];
    const float* conv1_w = (const float*)d_in[5];
    const float* conv1_b = (const float*)d_in[6];
    float* out = (float*)d_out;

    float *theta_p, *phi_p, *expS_p, *f_p;
    cudaGetSymbolAddress((void**)&theta_p, g_theta);
    cudaGetSymbolAddress((void**)&phi_p,   g_phi);
    cudaGetSymbolAddress((void**)&expS_p,  g_expS);
    cudaGetSymbolAddress((void**)&f_p,     g_f);

    dim3 blk(256);
    dim3 grid_conv(HWD / 128, CC / 128, NB);     // (32, 2, 4)
    dim3 grid_s(HWD / 128, HWD / 128, NB);       // (32, 32, 4)

    conv_gemm_kernel<<<grid_conv, blk>>>(theta_w, theta_b, x, nullptr, theta_p);
    conv_gemm_kernel<<<grid_conv, blk>>>(phi_w,   phi_b,   x, nullptr, phi_p);
    scores_exp_kernel<<<grid_s, blk>>>(theta_p, phi_p, expS_p);
    pv_kernel<<<grid_conv, blk>>>(x, expS_p, f_p);
    conv_gemm_kernel<<<grid_conv, blk>>>(conv1_w, conv1_b, f_p, x, out);
}

// round 8
// speedup vs baseline: 2.3589x; 2.3589x over previous
#include <cuda_runtime.h>
#include <cstdint>
#include <cstddef>

// Problem constants
#define NB  4
#define CC  256
#define HWD 4096

// ---------------------------------------------------------------------------
// Static device scratch (no allocation allowed)
// ---------------------------------------------------------------------------
__device__ float g_thetaT[(size_t)NB * HWD * CC];   // 16 MB, [n][p][c] c-contig
__device__ float g_phiT[(size_t)NB * HWD * CC];     // 16 MB, [n][q][c]
__device__ float g_expS[(size_t)NB * HWD * HWD];    // 256 MB, [n][p][q]
__device__ float g_rowsum[NB * HWD];                // 64 KB
__device__ float g_f[(size_t)NB * CC * HWD];        // 16 MB

// ---------------------------------------------------------------------------
// tf32 helpers (sm_80-baseline PTX — no 'a'-suffix features)
// ---------------------------------------------------------------------------
__device__ __forceinline__ uint32_t f2tf32(float v) {
    uint32_t r;
    asm("cvt.rna.tf32.f32 %0, %1;" : "=r"(r) : "f"(v));
    return r;
}

__device__ __forceinline__ void mma_tf32(float d[4],
                                         uint32_t a0, uint32_t a1,
                                         uint32_t a2, uint32_t a3,
                                         uint32_t b0, uint32_t b1)
{
    asm volatile(
        "mma.sync.aligned.m16n8k8.row.col.f32.tf32.tf32.f32 "
        "{%0,%1,%2,%3}, {%4,%5,%6,%7}, {%8,%9}, {%0,%1,%2,%3};\n"
        : "+f"(d[0]), "+f"(d[1]), "+f"(d[2]), "+f"(d[3])
        : "r"(a0), "r"(a1), "r"(a2), "r"(a3), "r"(b0), "r"(b1));
}

#define SMS 36   // smem row stride in 32-bit words (36 -> conflict-free quads)

// ---------------------------------------------------------------------------
// rowsum zero-init
// ---------------------------------------------------------------------------
__global__ void zero_rowsum_kernel(float* __restrict__ rowsum)
{
    rowsum[blockIdx.x * 256 + threadIdx.x] = 0.f;
}

// ---------------------------------------------------------------------------
// Scores (tf32 MMA): expS[n,p,q] = exp( (sum_c thT[p,c]*phT[q,c]) / 16 )
// Block tile 128(p) x 128(q), K = C = 256 in chunks of 32.
// 8 warps: wm in 0..3 (32 p-rows each), wn in 0..1 (64 q-cols each).
// Epilogue also accumulates softmax row sums (quad-shfl + atomicAdd).
// ---------------------------------------------------------------------------
__global__ __launch_bounds__(256, 2)
void scores_mma_kernel(const float* __restrict__ thT,
                       const float* __restrict__ phT,
                       float* __restrict__ expS,
                       float* __restrict__ rowsum)
{
    __shared__ uint32_t As[128 * SMS];
    __shared__ uint32_t Bs[128 * SMS];

    const int t    = threadIdx.x;
    const int lane = t & 31;
    const int wid  = t >> 5;
    const int g    = lane >> 2;      // group id 0..7
    const int tq   = lane & 3;       // thread-in-group 0..3
    const int wm   = wid & 3;        // 0..3
    const int wn   = wid >> 2;       // 0..1

    const int q0 = blockIdx.x * 128;
    const int p0 = blockIdx.y * 128;
    const int n  = blockIdx.z;

    const float* Ag = thT + ((size_t)n * HWD + p0) * CC;
    const float* Bg = phT + ((size_t)n * HWD + q0) * CC;

    float d[2][8][4];
#pragma unroll
    for (int mt = 0; mt < 2; ++mt)
#pragma unroll
        for (int nt = 0; nt < 8; ++nt)
#pragma unroll
            for (int j = 0; j < 4; ++j) d[mt][nt][j] = 0.f;

    for (int kt = 0; kt < CC; kt += 32) {
#pragma unroll
        for (int i = 0; i < 4; ++i) {
            int v  = t + i * 256;
            int r  = v >> 3;
            int kq = (v & 7) << 2;
            float4 a4 = *(const float4*)(Ag + (size_t)r * CC + kt + kq);
            As[r * SMS + kq + 0] = f2tf32(a4.x);
            As[r * SMS + kq + 1] = f2tf32(a4.y);
            As[r * SMS + kq + 2] = f2tf32(a4.z);
            As[r * SMS + kq + 3] = f2tf32(a4.w);
            float4 b4 = *(const float4*)(Bg + (size_t)r * CC + kt + kq);
            Bs[r * SMS + kq + 0] = f2tf32(b4.x);
            Bs[r * SMS + kq + 1] = f2tf32(b4.y);
            Bs[r * SMS + kq + 2] = f2tf32(b4.z);
            Bs[r * SMS + kq + 3] = f2tf32(b4.w);
        }
        __syncthreads();
#pragma unroll
        for (int kk = 0; kk < 32; kk += 8) {
            uint32_t b[8][2];
#pragma unroll
            for (int nt = 0; nt < 8; ++nt) {
                int br = wn * 64 + nt * 8 + g;
                b[nt][0] = Bs[br * SMS + kk + tq];
                b[nt][1] = Bs[br * SMS + kk + tq + 4];
            }
#pragma unroll
            for (int mt = 0; mt < 2; ++mt) {
                int ar = wm * 32 + mt * 16 + g;
                uint32_t a0 = As[ar * SMS + kk + tq];
                uint32_t a1 = As[(ar + 8) * SMS + kk + tq];
                uint32_t a2 = As[ar * SMS + kk + tq + 4];
                uint32_t a3 = As[(ar + 8) * SMS + kk + tq + 4];
#pragma unroll
                for (int nt = 0; nt < 8; ++nt)
                    mma_tf32(d[mt][nt], a0, a1, a2, a3, b[nt][0], b[nt][1]);
            }
        }
        __syncthreads();
    }

    // Epilogue: exp, store, row sums
    float* Sn = expS + (size_t)n * HWD * HWD;
    float rs[2][2] = {{0.f, 0.f}, {0.f, 0.f}};
#pragma unroll
    for (int mt = 0; mt < 2; ++mt) {
        const int row = p0 + wm * 32 + mt * 16 + g;
#pragma unroll
        for (int nt = 0; nt < 8; ++nt) {
            const int col = q0 + wn * 64 + nt * 8 + 2 * tq;
            float e0 = __expf(d[mt][nt][0] * 0.0625f);
            float e1 = __expf(d[mt][nt][1] * 0.0625f);
            float e2 = __expf(d[mt][nt][2] * 0.0625f);
            float e3 = __expf(d[mt][nt][3] * 0.0625f);
            *(float2*)(Sn + (size_t)row * HWD + col)       = make_float2(e0, e1);
            *(float2*)(Sn + (size_t)(row + 8) * HWD + col) = make_float2(e2, e3);
            rs[mt][0] += e0 + e1;
            rs[mt][1] += e2 + e3;
        }
    }
#pragma unroll
    for (int mt = 0; mt < 2; ++mt)
#pragma unroll
        for (int hh = 0; hh < 2; ++hh) {
            float v = rs[mt][hh];
            v += __shfl_xor_sync(0xFFFFFFFF, v, 1);
            v += __shfl_xor_sync(0xFFFFFFFF, v, 2);
            if (tq == 0)
                atomicAdd(&rowsum[n * HWD + p0 + wm * 32 + mt * 16 + g + hh * 8], v);
        }
}

// ---------------------------------------------------------------------------
// PV (tf32 MMA): f[n,c,p] = (sum_q x[c,q]*expS[p,q]) / rowsum[p]
// Block tile 128(c) x 128(p), K = HW = 4096 in chunks of 32.
// ---------------------------------------------------------------------------
__global__ __launch_bounds__(256, 2)
void pv_mma_kernel(const float* __restrict__ x,
                   const float* __restrict__ expS,
                   const float* __restrict__ rowsum,
                   float* __restrict__ f)
{
    __shared__ uint32_t As[128 * SMS];
    __shared__ uint32_t Bs[128 * SMS];
    __shared__ float rinv[128];

    const int t    = threadIdx.x;
    const int lane = t & 31;
    const int wid  = t >> 5;
    const int g    = lane >> 2;
    const int tq   = lane & 3;
    const int wm   = wid & 3;
    const int wn   = wid >> 2;

    const int p0 = blockIdx.x * 128;
    const int c0 = blockIdx.y * 128;
    const int n  = blockIdx.z;

    if (t < 128) rinv[t] = 1.0f / rowsum[n * HWD + p0 + t];

    const float* Ag = x    + (size_t)n * CC * HWD + (size_t)c0 * HWD;
    const float* Bg = expS + (size_t)n * HWD * HWD + (size_t)p0 * HWD;

    float d[2][8][4];
#pragma unroll
    for (int mt = 0; mt < 2; ++mt)
#pragma unroll
        for (int nt = 0; nt < 8; ++nt)
#pragma unroll
            for (int j = 0; j < 4; ++j) d[mt][nt][j] = 0.f;

    for (int kt = 0; kt < HWD; kt += 32) {
#pragma unroll
        for (int i = 0; i < 4; ++i) {
            int v  = t + i * 256;
            int r  = v >> 3;
            int kq = (v & 7) << 2;
            float4 a4 = *(const float4*)(Ag + (size_t)r * HWD + kt + kq);
            As[r * SMS + kq + 0] = f2tf32(a4.x);
            As[r * SMS + kq + 1] = f2tf32(a4.y);
            As[r * SMS + kq + 2] = f2tf32(a4.z);
            As[r * SMS + kq + 3] = f2tf32(a4.w);
            float4 b4 = *(const float4*)(Bg + (size_t)r * HWD + kt + kq);
            Bs[r * SMS + kq + 0] = f2tf32(b4.x);
            Bs[r * SMS + kq + 1] = f2tf32(b4.y);
            Bs[r * SMS + kq + 2] = f2tf32(b4.z);
            Bs[r * SMS + kq + 3] = f2tf32(b4.w);
        }
        __syncthreads();
#pragma unroll
        for (int kk = 0; kk < 32; kk += 8) {
            uint32_t b[8][2];
#pragma unroll
            for (int nt = 0; nt < 8; ++nt) {
                int br = wn * 64 + nt * 8 + g;
                b[nt][0] = Bs[br * SMS + kk + tq];
                b[nt][1] = Bs[br * SMS + kk + tq + 4];
            }
#pragma unroll
            for (int mt = 0; mt < 2; ++mt) {
                int ar = wm * 32 + mt * 16 + g;
                uint32_t a0 = As[ar * SMS + kk + tq];
                uint32_t a1 = As[(ar + 8) * SMS + kk + tq];
                uint32_t a2 = As[ar * SMS + kk + tq + 4];
                uint32_t a3 = As[(ar + 8) * SMS + kk + tq + 4];
#pragma unroll
                for (int nt = 0; nt < 8; ++nt)
                    mma_tf32(d[mt][nt], a0, a1, a2, a3, b[nt][0], b[nt][1]);
            }
        }
        __syncthreads();
    }

    float* Fn = f + (size_t)n * CC * HWD;
#pragma unroll
    for (int mt = 0; mt < 2; ++mt) {
        const int row = c0 + wm * 32 + mt * 16 + g;
#pragma unroll
        for (int nt = 0; nt < 8; ++nt) {
            const int lc  = wn * 64 + nt * 8 + 2 * tq;
            const int col = p0 + lc;
            float r0 = rinv[lc], r1 = rinv[lc + 1];
            *(float2*)(Fn + (size_t)row * HWD + col) =
                make_float2(d[mt][nt][0] * r0, d[mt][nt][1] * r1);
            *(float2*)(Fn + (size_t)(row + 8) * HWD + col) =
                make_float2(d[mt][nt][2] * r0, d[mt][nt][3] * r1);
        }
    }
}

// ---------------------------------------------------------------------------
// 1x1 conv GEMM (SIMT fp32), standard-layout output (+ optional residual).
// ---------------------------------------------------------------------------
__global__ __launch_bounds__(256, 2)
void conv_gemm_kernel(const float* __restrict__ W,
                      const float* __restrict__ bias,
                      const float* __restrict__ X,
                      const float* __restrict__ resid,
                      float* __restrict__ out)
{
    __shared__ float Ws[16][132];
    __shared__ float Xs[16][128];

    const int t  = threadIdx.x;
    const int tx = t & 15;
    const int ty = t >> 4;
    const int p0 = blockIdx.x * 128;
    const int o0 = blockIdx.y * 128;
    const int n  = blockIdx.z;

    const float* Xn = X + (size_t)n * CC * HWD;

    float acc[2][2][4][4];
#pragma unroll
    for (int a = 0; a < 2; ++a)
#pragma unroll
        for (int b = 0; b < 2; ++b)
#pragma unroll
            for (int i = 0; i < 4; ++i)
#pragma unroll
                for (int j = 0; j < 4; ++j) acc[a][b][i][j] = 0.f;

    for (int kt = 0; kt < CC; kt += 16) {
#pragma unroll
        for (int i = 0; i < 2; ++i) {
            int v  = t + i * 256;
            int r  = v >> 2;
            int kk = (v & 3) << 2;
            float4 w4 = *(const float4*)(W + (size_t)(o0 + r) * CC + kt + kk);
            Ws[kk + 0][r] = w4.x; Ws[kk + 1][r] = w4.y;
            Ws[kk + 2][r] = w4.z; Ws[kk + 3][r] = w4.w;
        }
#pragma unroll
        for (int i = 0; i < 2; ++i) {
            int v  = t + i * 256;
            int k  = v >> 5;
            int p4 = (v & 31) << 2;
            *(float4*)&Xs[k][p4] =
                *(const float4*)(Xn + (size_t)(kt + k) * HWD + p0 + p4);
        }
        __syncthreads();
#pragma unroll
        for (int k = 0; k < 16; ++k) {
            float a[2][4], b[2][4];
            *(float4*)a[0] = *(const float4*)&Ws[k][ty * 4];
            *(float4*)a[1] = *(const float4*)&Ws[k][64 + ty * 4];
            *(float4*)b[0] = *(const float4*)&Xs[k][tx * 4];
            *(float4*)b[1] = *(const float4*)&Xs[k][64 + tx * 4];
#pragma unroll
            for (int ih = 0; ih < 2; ++ih)
#pragma unroll
                for (int jh = 0; jh < 2; ++jh)
#pragma unroll
                    for (int i = 0; i < 4; ++i)
#pragma unroll
                        for (int j = 0; j < 4; ++j)
                            acc[ih][jh][i][j] += a[ih][i] * b[jh][j];
        }
        __syncthreads();
    }

#pragma unroll
    for (int ih = 0; ih < 2; ++ih) {
#pragma unroll
        for (int i = 0; i < 4; ++i) {
            const int row = o0 + ih * 64 + ty * 4 + i;
            const float bv = bias[row];
#pragma unroll
            for (int jh = 0; jh < 2; ++jh) {
                const int col = p0 + jh * 64 + tx * 4;
                float4 v;
                v.x = acc[ih][jh][i][0] + bv;
                v.y = acc[ih][jh][i][1] + bv;
                v.z = acc[ih][jh][i][2] + bv;
                v.w = acc[ih][jh][i][3] + bv;
                const size_t off = (size_t)n * CC * HWD + (size_t)row * HWD + col;
                if (resid) {
                    float4 rr = *(const float4*)(resid + off);
                    v.x += rr.x; v.y += rr.y; v.z += rr.z; v.w += rr.w;
                }
                *(float4*)(out + off) = v;
            }
        }
    }
}

// ---------------------------------------------------------------------------
// 1x1 conv GEMM with TRANSPOSED fp32 output: outT[n][p][o] (channel-contig),
// feeding the tensor-core scores kernel.
// ---------------------------------------------------------------------------
__global__ __launch_bounds__(256, 2)
void conv_gemm_t_kernel(const float* __restrict__ W,
                        const float* __restrict__ bias,
                        const float* __restrict__ X,
                        float* __restrict__ outT)
{
    __shared__ float Ws[16][132];
    __shared__ float Xs[16][128];

    const int t  = threadIdx.x;
    const int tx = t & 15;
    const int ty = t >> 4;
    const int p0 = blockIdx.x * 128;
    const int o0 = blockIdx.y * 128;
    const int n  = blockIdx.z;

    const float* Xn = X + (size_t)n * CC * HWD;

    float acc[2][2][4][4];
#pragma unroll
    for (int a = 0; a < 2; ++a)
#pragma unroll
        for (int b = 0; b < 2; ++b)
#pragma unroll
            for (int i = 0; i < 4; ++i)
#pragma unroll
                for (int j = 0; j < 4; ++j) acc[a][b][i][j] = 0.f;

    for (int kt = 0; kt < CC; kt += 16) {
#pragma unroll
        for (int i = 0; i < 2; ++i) {
            int v  = t + i * 256;
            int r  = v >> 2;
            int kk = (v & 3) << 2;
            float4 w4 = *(const float4*)(W + (size_t)(o0 + r) * CC + kt + kk);
            Ws[kk + 0][r] = w4.x; Ws[kk + 1][r] = w4.y;
            Ws[kk + 2][r] = w4.z; Ws[kk + 3][r] = w4.w;
        }
#pragma unroll
        for (int i = 0; i < 2; ++i) {
            int v  = t + i * 256;
            int k  = v >> 5;
            int p4 = (v & 31) << 2;
            *(float4*)&Xs[k][p4] =
                *(const float4*)(Xn + (size_t)(kt + k) * HWD + p0 + p4);
        }
        __syncthreads();
#pragma unroll
        for (int k = 0; k < 16; ++k) {
            float a[2][4], b[2][4];
            *(float4*)a[0] = *(const float4*)&Ws[k][ty * 4];
            *(float4*)a[1] = *(const float4*)&Ws[k][64 + ty * 4];
            *(float4*)b[0] = *(const float4*)&Xs[k][tx * 4];
            *(float4*)b[1] = *(const float4*)&Xs[k][64 + tx * 4];
#pragma unroll
            for (int ih = 0; ih < 2; ++ih)
#pragma unroll
                for (int jh = 0; jh < 2; ++jh)
#pragma unroll
                    for (int i = 0; i < 4; ++i)
#pragma unroll
                        for (int j = 0; j < 4; ++j)
                            acc[ih][jh][i][j] += a[ih][i] * b[jh][j];
        }
        __syncthreads();
    }

    float bv[2][4];
#pragma unroll
    for (int ih = 0; ih < 2; ++ih)
#pragma unroll
        for (int i = 0; i < 4; ++i) bv[ih][i] = bias[o0 + ih * 64 + ty * 4 + i];

    float* On = outT + (size_t)n * HWD * CC;
#pragma unroll
    for (int jh = 0; jh < 2; ++jh) {
#pragma unroll
        for (int j = 0; j < 4; ++j) {
            const int p = p0 + jh * 64 + tx * 4 + j;
#pragma unroll
            for (int ih = 0; ih < 2; ++ih) {
                const int ob = o0 + ih * 64 + ty * 4;
                float4 v;
                v.x = acc[ih][jh][0][j] + bv[ih][0];
                v.y = acc[ih][jh][1][j] + bv[ih][1];
                v.z = acc[ih][jh][2][j] + bv[ih][2];
                v.w = acc[ih][jh][3][j] + bv[ih][3];
                *(float4*)(On + (size_t)p * CC + ob) = v;
            }
        }
    }
}

// ---------------------------------------------------------------------------
// Launch
// ---------------------------------------------------------------------------
extern "C" void kernel_launch(void* const* d_in, const int* in_sizes, int n_in,
                              void* d_out, int out_size)
{
    (void)in_sizes; (void)n_in; (void)out_size;
    const float* x       = (const float*)d_in[0];
    const float* theta_w = (const float*)d_in[1];
    const float* theta_b = (const float*)d_in[2];
    const float* phi_w   = (const float*)d_in[3];
    const float* phi_b   = (const float*)d_in[4];
    const float* conv1_w = (const float*)d_in[5];
    const float* conv1_b = (const float*)d_in[6];
    float* out = (float*)d_out;

    float *thT_p, *phT_p, *expS_p, *rsum_p, *f_p;
    cudaGetSymbolAddress((void**)&thT_p,  g_thetaT);
    cudaGetSymbolAddress((void**)&phT_p,  g_phiT);
    cudaGetSymbolAddress((void**)&expS_p, g_expS);
    cudaGetSymbolAddress((void**)&rsum_p, g_rowsum);
    cudaGetSymbolAddress((void**)&f_p,    g_f);

    dim3 blk(256);
    dim3 grid_conv(HWD / 128, CC / 128, NB);   // (32, 2, 4)
    dim3 grid_s(HWD / 128, HWD / 128, NB);     // (32, 32, 4)
    dim3 grid_pv(HWD / 128, CC / 128, NB);     // (32, 2, 4)

    zero_rowsum_kernel<<<NB * HWD / 256, blk>>>(rsum_p);
    conv_gemm_t_kernel<<<grid_conv, blk>>>(theta_w, theta_b, x, thT_p);
    conv_gemm_t_kernel<<<grid_conv, blk>>>(phi_w,   phi_b,   x, phT_p);
    scores_mma_kernel<<<grid_s, blk>>>(thT_p, phT_p, expS_p, rsum_p);
    pv_mma_kernel<<<grid_pv, blk>>>(x, expS_p, rsum_p, f_p);
    conv_gemm_kernel<<<grid_conv, blk>>>(conv1_w, conv1_b, f_p, x, out);
}

// round 9
// speedup vs baseline: 3.0660x; 1.2998x over previous
#include <cuda_runtime.h>
#include <cuda_bf16.h>
#include <cstdint>
#include <cstddef>

// Problem constants
#define NB  4
#define CC  256
#define HWD 4096

// ---------------------------------------------------------------------------
// Static device scratch (no allocation allowed)
// ---------------------------------------------------------------------------
__device__ float g_thetaT[(size_t)NB * HWD * CC];   // 16 MB, [n][p][c] c-contig
__device__ float g_phiT[(size_t)NB * HWD * CC];     // 16 MB, [n][q][c]
__device__ float g_expS[(size_t)NB * HWD * HWD];    // 256 MB, [n][p][q]
__device__ float g_rowsum[NB * HWD];                // 64 KB
__device__ float g_f[(size_t)NB * CC * HWD];        // 16 MB

// ---------------------------------------------------------------------------
// Helpers (all sm_80/75-baseline PTX — no 'a'-suffix features)
// ---------------------------------------------------------------------------
__device__ __forceinline__ uint32_t smem_u32(const void* p) {
    uint32_t a;
    asm("{ .reg .u64 t; cvta.to.shared.u64 t, %1; cvt.u32.u64 %0, t; }"
        : "=r"(a) : "l"(p));
    return a;
}

__device__ __forceinline__ uint32_t f22bf(float x, float y) {
    __nv_bfloat162 h = __floats2bfloat162_rn(x, y);   // low = x (lower k)
    return *reinterpret_cast<uint32_t*>(&h);
}

__device__ __forceinline__ void ldsm_x4(uint32_t& r0, uint32_t& r1,
                                        uint32_t& r2, uint32_t& r3,
                                        uint32_t addr)
{
    asm volatile("ldmatrix.sync.aligned.m8n8.x4.shared.b16 {%0,%1,%2,%3}, [%4];"
                 : "=r"(r0), "=r"(r1), "=r"(r2), "=r"(r3) : "r"(addr));
}

__device__ __forceinline__ void mma_bf16(float d[4],
                                         uint32_t a0, uint32_t a1,
                                         uint32_t a2, uint32_t a3,
                                         uint32_t b0, uint32_t b1)
{
    asm volatile(
        "mma.sync.aligned.m16n8k16.row.col.f32.bf16.bf16.f32 "
        "{%0,%1,%2,%3}, {%4,%5,%6,%7}, {%8,%9}, {%0,%1,%2,%3};\n"
        : "+f"(d[0]), "+f"(d[1]), "+f"(d[2]), "+f"(d[3])
        : "r"(a0), "r"(a1), "r"(a2), "r"(a3), "r"(b0), "r"(b1));
}

#define SMH 40   // smem row stride in bf16 halfs (80 B) -> LDSM conflict-free

// ---------------------------------------------------------------------------
// rowsum zero-init
// ---------------------------------------------------------------------------
__global__ void zero_rowsum_kernel(float* __restrict__ rowsum)
{
    rowsum[blockIdx.x * 256 + threadIdx.x] = 0.f;
}

// ---------------------------------------------------------------------------
// Scores (bf16 MMA): expS[n,p,q] = exp( (sum_c thT[p,c]*phT[q,c]) / 16 )
// Block tile 128(p) x 128(q), K = C = 256 in chunks of 32 (2 k16 steps).
// 8 warps: wm 0..3 (32 p-rows), wn 0..1 (64 q-cols). ldmatrix fragments.
// Epilogue accumulates softmax row sums (quad-shfl + atomicAdd).
// ---------------------------------------------------------------------------
__global__ __launch_bounds__(256, 2)
void scores_mma_kernel(const float* __restrict__ thT,
                       const float* __restrict__ phT,
                       float* __restrict__ expS,
                       float* __restrict__ rowsum)
{
    __shared__ __align__(16) uint16_t As[128 * SMH];
    __shared__ __align__(16) uint16_t Bs[128 * SMH];

    const int t    = threadIdx.x;
    const int lane = t & 31;
    const int wid  = t >> 5;
    const int g    = lane >> 2;
    const int tq   = lane & 3;
    const int wm   = wid & 3;
    const int wn   = wid >> 2;

    const int q0 = blockIdx.x * 128;
    const int p0 = blockIdx.y * 128;
    const int n  = blockIdx.z;

    const float* Ag = thT + ((size_t)n * HWD + p0) * CC;
    const float* Bg = phT + ((size_t)n * HWD + q0) * CC;

    // ldmatrix per-lane base addresses
    const uint32_t sA = smem_u32(As), sB = smem_u32(Bs);
    uint32_t a_addr[2], b_addr[4];
#pragma unroll
    for (int mt = 0; mt < 2; ++mt) {
        int rowA = wm * 32 + mt * 16 + (lane & 15);
        int col  = (lane >> 4) * 8;
        a_addr[mt] = sA + (uint32_t)(rowA * SMH + col) * 2;
    }
#pragma unroll
    for (int ntp = 0; ntp < 4; ++ntp) {
        int rowB = wn * 64 + ntp * 16 + ((lane >> 4) & 1) * 8 + (lane & 7);
        int col  = ((lane >> 3) & 1) * 8;
        b_addr[ntp] = sB + (uint32_t)(rowB * SMH + col) * 2;
    }

    float d[2][8][4];
#pragma unroll
    for (int mt = 0; mt < 2; ++mt)
#pragma unroll
        for (int nt = 0; nt < 8; ++nt)
#pragma unroll
            for (int j = 0; j < 4; ++j) d[mt][nt][j] = 0.f;

    for (int kt = 0; kt < CC; kt += 32) {
        // load + fp32->bf16 convert (rows of 32 k, 8 threads/row)
#pragma unroll
        for (int i = 0; i < 4; ++i) {
            int v  = t + i * 256;
            int r  = v >> 3;
            int kq = (v & 7) << 2;
            float4 a4 = *(const float4*)(Ag + (size_t)r * CC + kt + kq);
            uint32_t* da = (uint32_t*)&As[r * SMH + kq];
            da[0] = f22bf(a4.x, a4.y);
            da[1] = f22bf(a4.z, a4.w);
            float4 b4 = *(const float4*)(Bg + (size_t)r * CC + kt + kq);
            uint32_t* db = (uint32_t*)&Bs[r * SMH + kq];
            db[0] = f22bf(b4.x, b4.y);
            db[1] = f22bf(b4.z, b4.w);
        }
        __syncthreads();
#pragma unroll
        for (int kh = 0; kh < 2; ++kh) {
            const uint32_t off = kh * 32;          // 16 halfs = 32 bytes
            uint32_t a[2][4], b[4][4];
#pragma unroll
            for (int mt = 0; mt < 2; ++mt)
                ldsm_x4(a[mt][0], a[mt][1], a[mt][2], a[mt][3], a_addr[mt] + off);
#pragma unroll
            for (int ntp = 0; ntp < 4; ++ntp)
                ldsm_x4(b[ntp][0], b[ntp][1], b[ntp][2], b[ntp][3], b_addr[ntp] + off);
#pragma unroll
            for (int mt = 0; mt < 2; ++mt)
#pragma unroll
                for (int nt = 0; nt < 8; ++nt)
                    mma_bf16(d[mt][nt], a[mt][0], a[mt][1], a[mt][2], a[mt][3],
                             b[nt >> 1][(nt & 1) * 2], b[nt >> 1][(nt & 1) * 2 + 1]);
        }
        __syncthreads();
    }

    // Epilogue: exp, store, row sums
    float* Sn = expS + (size_t)n * HWD * HWD;
    float rs[2][2] = {{0.f, 0.f}, {0.f, 0.f}};
#pragma unroll
    for (int mt = 0; mt < 2; ++mt) {
        const int row = p0 + wm * 32 + mt * 16 + g;
#pragma unroll
        for (int nt = 0; nt < 8; ++nt) {
            const int col = q0 + wn * 64 + nt * 8 + 2 * tq;
            float e0 = __expf(d[mt][nt][0] * 0.0625f);
            float e1 = __expf(d[mt][nt][1] * 0.0625f);
            float e2 = __expf(d[mt][nt][2] * 0.0625f);
            float e3 = __expf(d[mt][nt][3] * 0.0625f);
            *(float2*)(Sn + (size_t)row * HWD + col)       = make_float2(e0, e1);
            *(float2*)(Sn + (size_t)(row + 8) * HWD + col) = make_float2(e2, e3);
            rs[mt][0] += e0 + e1;
            rs[mt][1] += e2 + e3;
        }
    }
#pragma unroll
    for (int mt = 0; mt < 2; ++mt)
#pragma unroll
        for (int hh = 0; hh < 2; ++hh) {
            float v = rs[mt][hh];
            v += __shfl_xor_sync(0xFFFFFFFF, v, 1);
            v += __shfl_xor_sync(0xFFFFFFFF, v, 2);
            if (tq == 0)
                atomicAdd(&rowsum[n * HWD + p0 + wm * 32 + mt * 16 + g + hh * 8], v);
        }
}

// ---------------------------------------------------------------------------
// PV (bf16 MMA): f[n,c,p] = (sum_q x[c,q]*expS[p,q]) / rowsum[p]
// Block tile 128(c) x 128(p), K = HW = 4096 in chunks of 32.
// ---------------------------------------------------------------------------
__global__ __launch_bounds__(256, 2)
void pv_mma_kernel(const float* __restrict__ x,
                   const float* __restrict__ expS,
                   const float* __restrict__ rowsum,
                   float* __restrict__ f)
{
    __shared__ __align__(16) uint16_t As[128 * SMH];
    __shared__ __align__(16) uint16_t Bs[128 * SMH];
    __shared__ float rinv[128];

    const int t    = threadIdx.x;
    const int lane = t & 31;
    const int wid  = t >> 5;
    const int g    = lane >> 2;
    const int tq   = lane & 3;
    const int wm   = wid & 3;
    const int wn   = wid >> 2;

    const int p0 = blockIdx.x * 128;
    const int c0 = blockIdx.y * 128;
    const int n  = blockIdx.z;

    if (t < 128) rinv[t] = 1.0f / rowsum[n * HWD + p0 + t];

    const float* Ag = x    + (size_t)n * CC * HWD + (size_t)c0 * HWD;
    const float* Bg = expS + (size_t)n * HWD * HWD + (size_t)p0 * HWD;

    const uint32_t sA = smem_u32(As), sB = smem_u32(Bs);
    uint32_t a_addr[2], b_addr[4];
#pragma unroll
    for (int mt = 0; mt < 2; ++mt) {
        int rowA = wm * 32 + mt * 16 + (lane & 15);
        int col  = (lane >> 4) * 8;
        a_addr[mt] = sA + (uint32_t)(rowA * SMH + col) * 2;
    }
#pragma unroll
    for (int ntp = 0; ntp < 4; ++ntp) {
        int rowB = wn * 64 + ntp * 16 + ((lane >> 4) & 1) * 8 + (lane & 7);
        int col  = ((lane >> 3) & 1) * 8;
        b_addr[ntp] = sB + (uint32_t)(rowB * SMH + col) * 2;
    }

    float d[2][8][4];
#pragma unroll
    for (int mt = 0; mt < 2; ++mt)
#pragma unroll
        for (int nt = 0; nt < 8; ++nt)
#pragma unroll
            for (int j = 0; j < 4; ++j) d[mt][nt][j] = 0.f;

    for (int kt = 0; kt < HWD; kt += 32) {
#pragma unroll
        for (int i = 0; i < 4; ++i) {
            int v  = t + i * 256;
            int r  = v >> 3;
            int kq = (v & 7) << 2;
            float4 a4 = *(const float4*)(Ag + (size_t)r * HWD + kt + kq);
            uint32_t* da = (uint32_t*)&As[r * SMH + kq];
            da[0] = f22bf(a4.x, a4.y);
            da[1] = f22bf(a4.z, a4.w);
            float4 b4 = *(const float4*)(Bg + (size_t)r * HWD + kt + kq);
            uint32_t* db = (uint32_t*)&Bs[r * SMH + kq];
            db[0] = f22bf(b4.x, b4.y);
            db[1] = f22bf(b4.z, b4.w);
        }
        __syncthreads();
#pragma unroll
        for (int kh = 0; kh < 2; ++kh) {
            const uint32_t off = kh * 32;
            uint32_t a[2][4], b[4][4];
#pragma unroll
            for (int mt = 0; mt < 2; ++mt)
                ldsm_x4(a[mt][0], a[mt][1], a[mt][2], a[mt][3], a_addr[mt] + off);
#pragma unroll
            for (int ntp = 0; ntp < 4; ++ntp)
                ldsm_x4(b[ntp][0], b[ntp][1], b[ntp][2], b[ntp][3], b_addr[ntp] + off);
#pragma unroll
            for (int mt = 0; mt < 2; ++mt)
#pragma unroll
                for (int nt = 0; nt < 8; ++nt)
                    mma_bf16(d[mt][nt], a[mt][0], a[mt][1], a[mt][2], a[mt][3],
                             b[nt >> 1][(nt & 1) * 2], b[nt >> 1][(nt & 1) * 2 + 1]);
        }
        __syncthreads();
    }

    float* Fn = f + (size_t)n * CC * HWD;
#pragma unroll
    for (int mt = 0; mt < 2; ++mt) {
        const int row = c0 + wm * 32 + mt * 16 + g;
#pragma unroll
        for (int nt = 0; nt < 8; ++nt) {
            const int lc  = wn * 64 + nt * 8 + 2 * tq;
            const int col = p0 + lc;
            float r0 = rinv[lc], r1 = rinv[lc + 1];
            *(float2*)(Fn + (size_t)row * HWD + col) =
                make_float2(d[mt][nt][0] * r0, d[mt][nt][1] * r1);
            *(float2*)(Fn + (size_t)(row + 8) * HWD + col) =
                make_float2(d[mt][nt][2] * r0, d[mt][nt][3] * r1);
        }
    }
}

// ---------------------------------------------------------------------------
// 1x1 conv GEMM (SIMT fp32), standard-layout output (+ optional residual).
// ---------------------------------------------------------------------------
__global__ __launch_bounds__(256, 2)
void conv_gemm_kernel(const float* __restrict__ W,
                      const float* __restrict__ bias,
                      const float* __restrict__ X,
                      const float* __restrict__ resid,
                      float* __restrict__ out)
{
    __shared__ float Ws[16][132];
    __shared__ float Xs[16][128];

    const int t  = threadIdx.x;
    const int tx = t & 15;
    const int ty = t >> 4;
    const int p0 = blockIdx.x * 128;
    const int o0 = blockIdx.y * 128;
    const int n  = blockIdx.z;

    const float* Xn = X + (size_t)n * CC * HWD;

    float acc[2][2][4][4];
#pragma unroll
    for (int a = 0; a < 2; ++a)
#pragma unroll
        for (int b = 0; b < 2; ++b)
#pragma unroll
            for (int i = 0; i < 4; ++i)
#pragma unroll
                for (int j = 0; j < 4; ++j) acc[a][b][i][j] = 0.f;

    for (int kt = 0; kt < CC; kt += 16) {
#pragma unroll
        for (int i = 0; i < 2; ++i) {
            int v  = t + i * 256;
            int r  = v >> 2;
            int kk = (v & 3) << 2;
            float4 w4 = *(const float4*)(W + (size_t)(o0 + r) * CC + kt + kk);
            Ws[kk + 0][r] = w4.x; Ws[kk + 1][r] = w4.y;
            Ws[kk + 2][r] = w4.z; Ws[kk + 3][r] = w4.w;
        }
#pragma unroll
        for (int i = 0; i < 2; ++i) {
            int v  = t + i * 256;
            int k  = v >> 5;
            int p4 = (v & 31) << 2;
            *(float4*)&Xs[k][p4] =
                *(const float4*)(Xn + (size_t)(kt + k) * HWD + p0 + p4);
        }
        __syncthreads();
#pragma unroll
        for (int k = 0; k < 16; ++k) {
            float a[2][4], b[2][4];
            *(float4*)a[0] = *(const float4*)&Ws[k][ty * 4];
            *(float4*)a[1] = *(const float4*)&Ws[k][64 + ty * 4];
            *(float4*)b[0] = *(const float4*)&Xs[k][tx * 4];
            *(float4*)b[1] = *(const float4*)&Xs[k][64 + tx * 4];
#pragma unroll
            for (int ih = 0; ih < 2; ++ih)
#pragma unroll
                for (int jh = 0; jh < 2; ++jh)
#pragma unroll
                    for (int i = 0; i < 4; ++i)
#pragma unroll
                        for (int j = 0; j < 4; ++j)
                            acc[ih][jh][i][j] += a[ih][i] * b[jh][j];
        }
        __syncthreads();
    }

#pragma unroll
    for (int ih = 0; ih < 2; ++ih) {
#pragma unroll
        for (int i = 0; i < 4; ++i) {
            const int row = o0 + ih * 64 + ty * 4 + i;
            const float bv = bias[row];
#pragma unroll
            for (int jh = 0; jh < 2; ++jh) {
                const int col = p0 + jh * 64 + tx * 4;
                float4 v;
                v.x = acc[ih][jh][i][0] + bv;
                v.y = acc[ih][jh][i][1] + bv;
                v.z = acc[ih][jh][i][2] + bv;
                v.w = acc[ih][jh][i][3] + bv;
                const size_t off = (size_t)n * CC * HWD + (size_t)row * HWD + col;
                if (resid) {
                    float4 rr = *(const float4*)(resid + off);
                    v.x += rr.x; v.y += rr.y; v.z += rr.z; v.w += rr.w;
                }
                *(float4*)(out + off) = v;
            }
        }
    }
}

// ---------------------------------------------------------------------------
// 1x1 conv GEMM with TRANSPOSED fp32 output: outT[n][p][o] (channel-contig),
// feeding the tensor-core scores kernel.
// ---------------------------------------------------------------------------
__global__ __launch_bounds__(256, 2)
void conv_gemm_t_kernel(const float* __restrict__ W,
                        const float* __restrict__ bias,
                        const float* __restrict__ X,
                        float* __restrict__ outT)
{
    __shared__ float Ws[16][132];
    __shared__ float Xs[16][128];

    const int t  = threadIdx.x;
    const int tx = t & 15;
    const int ty = t >> 4;
    const int p0 = blockIdx.x * 128;
    const int o0 = blockIdx.y * 128;
    const int n  = blockIdx.z;

    const float* Xn = X + (size_t)n * CC * HWD;

    float acc[2][2][4][4];
#pragma unroll
    for (int a = 0; a < 2; ++a)
#pragma unroll
        for (int b = 0; b < 2; ++b)
#pragma unroll
            for (int i = 0; i < 4; ++i)
#pragma unroll
                for (int j = 0; j < 4; ++j) acc[a][b][i][j] = 0.f;

    for (int kt = 0; kt < CC; kt += 16) {
#pragma unroll
        for (int i = 0; i < 2; ++i) {
            int v  = t + i * 256;
            int r  = v >> 2;
            int kk = (v & 3) << 2;
            float4 w4 = *(const float4*)(W + (size_t)(o0 + r) * CC + kt + kk);
            Ws[kk + 0][r] = w4.x; Ws[kk + 1][r] = w4.y;
            Ws[kk + 2][r] = w4.z; Ws[kk + 3][r] = w4.w;
        }
#pragma unroll
        for (int i = 0; i < 2; ++i) {
            int v  = t + i * 256;
            int k  = v >> 5;
            int p4 = (v & 31) << 2;
            *(float4*)&Xs[k][p4] =
                *(const float4*)(Xn + (size_t)(kt + k) * HWD + p0 + p4);
        }
        __syncthreads();
#pragma unroll
        for (int k = 0; k < 16; ++k) {
            float a[2][4], b[2][4];
            *(float4*)a[0] = *(const float4*)&Ws[k][ty * 4];
            *(float4*)a[1] = *(const float4*)&Ws[k][64 + ty * 4];
            *(float4*)b[0] = *(const float4*)&Xs[k][tx * 4];
            *(float4*)b[1] = *(const float4*)&Xs[k][64 + tx * 4];
#pragma unroll
            for (int ih = 0; ih < 2; ++ih)
#pragma unroll
                for (int jh = 0; jh < 2; ++jh)
#pragma unroll
                    for (int i = 0; i < 4; ++i)
#pragma unroll
                        for (int j = 0; j < 4; ++j)
                            acc[ih][jh][i][j] += a[ih][i] * b[jh][j];
        }
        __syncthreads();
    }

    float bv[2][4];
#pragma unroll
    for (int ih = 0; ih < 2; ++ih)
#pragma unroll
        for (int i = 0; i < 4; ++i) bv[ih][i] = bias[o0 + ih * 64 + ty * 4 + i];

    float* On = outT + (size_t)n * HWD * CC;
#pragma unroll
    for (int jh = 0; jh < 2; ++jh) {
#pragma unroll
        for (int j = 0; j < 4; ++j) {
            const int p = p0 + jh * 64 + tx * 4 + j;
#pragma unroll
            for (int ih = 0; ih < 2; ++ih) {
                const int ob = o0 + ih * 64 + ty * 4;
                float4 v;
                v.x = acc[ih][jh][0][j] + bv[ih][0];
                v.y = acc[ih][jh][1][j] + bv[ih][1];
                v.z = acc[ih][jh][2][j] + bv[ih][2];
                v.w = acc[ih][jh][3][j] + bv[ih][3];
                *(float4*)(On + (size_t)p * CC + ob) = v;
            }
        }
    }
}

// ---------------------------------------------------------------------------
// Launch
// ---------------------------------------------------------------------------
extern "C" void kernel_launch(void* const* d_in, const int* in_sizes, int n_in,
                              void* d_out, int out_size)
{
    (void)in_sizes; (void)n_in; (void)out_size;
    const float* x       = (const float*)d_in[0];
    const float* theta_w = (const float*)d_in[1];
    const float* theta_b = (const float*)d_in[2];
    const float* phi_w   = (const float*)d_in[3];
    const float* phi_b   = (const float*)d_in[4];
    const float* conv1_w = (const float*)d_in[5];
    const float* conv1_b = (const float*)d_in[6];
    float* out = (float*)d_out;

    float *thT_p, *phT_p, *expS_p, *rsum_p, *f_p;
    cudaGetSymbolAddress((void**)&thT_p,  g_thetaT);
    cudaGetSymbolAddress((void**)&phT_p,  g_phiT);
    cudaGetSymbolAddress((void**)&expS_p, g_expS);
    cudaGetSymbolAddress((void**)&rsum_p, g_rowsum);
    cudaGetSymbolAddress((void**)&f_p,    g_f);

    dim3 blk(256);
    dim3 grid_conv(HWD / 128, CC / 128, NB);   // (32, 2, 4)
    dim3 grid_s(HWD / 128, HWD / 128, NB);     // (32, 32, 4)
    dim3 grid_pv(HWD / 128, CC / 128, NB);     // (32, 2, 4)

    zero_rowsum_kernel<<<NB * HWD / 256, blk>>>(rsum_p);
    conv_gemm_t_kernel<<<grid_conv, blk>>>(theta_w, theta_b, x, thT_p);
    conv_gemm_t_kernel<<<grid_conv, blk>>>(phi_w,   phi_b,   x, phT_p);
    scores_mma_kernel<<<grid_s, blk>>>(thT_p, phT_p, expS_p, rsum_p);
    pv_mma_kernel<<<grid_pv, blk>>>(x, expS_p, rsum_p, f_p);
    conv_gemm_kernel<<<grid_conv, blk>>>(conv1_w, conv1_b, f_p, x, out);
}